// round 15
// baseline (speedup 1.0000x reference)
#include <cuda_runtime.h>
#include <cuda_fp16.h>
#include <math.h>
#include <stdint.h>

#define BB   2048
#define INN  512
#define HH   512
#define KFR  32
#define OUTN 512
#define KD   1536            // IN + 2H (combined_d width)
#define KC   1024            // IN + H
#define BH   (BB*HH)

#define OFF_WI   0
#define OFF_WO   (512*1024)
#define OFF_WC   (2*512*1024)
#define OFF_WF   (3*512*1024)
#define OFF_WOUT (3*512*1024 + 512*1536)
#define W_TOTAL  (OFF_WOUT + 512*512)

// gates: 128x128 tile, stage = A+B = 32KB, 3 stages = 96KB -> 2 CTAs/SM
#define TILE_B   16384
#define STAGE_B  (2*TILE_B)
#define NSTAGE   3
#define SMEM_TOT (NSTAGE*STAGE_B)   // 98304

// out: 64x64 tile, stage = A 8KB + B 8KB = 16KB, 3 stages = 48KB
#define OA_TILE_B 8192
#define OSTAGE_B  (2*OA_TILE_B)
#define OSMEM_TOT (NSTAGE*OSTAGE_B)  // 49152

// flat conversion index ranges (float4 units)
#define CVF4_COMB  (BB*KD/4)
#define CVF4_W1    (512*1024/4)
#define CVF4_WF    (512*1536/4)
#define CVF4_WOUT  (512*512/4)
#define CVF4_TOTAL (CVF4_COMB + 3*CVF4_W1 + CVF4_WF + CVF4_WOUT)

// ---------------- static device scratch (fp16) ----------------
__device__ __half g_comb_h[BB*KD];
__device__ __half g_w_h[W_TOTAL];
__device__ __half g_hid_h[BH];
__device__ float g_z[4][BH];          // pre-activations: 0=i, 1=o, 2=c, 3=f

// ---------------- PTX helpers (baseline ISA only) ----------------
__device__ __forceinline__ uint32_t smem_u32(const void* p) {
    return (uint32_t)__cvta_generic_to_shared(p);
}

__device__ __forceinline__ void cp16(uint32_t daddr, const void* g) {
    asm volatile("cp.async.cg.shared.global [%0], [%1], 16;" :: "r"(daddr), "l"(g) : "memory");
}
#define CP_COMMIT() asm volatile("cp.async.commit_group;" ::: "memory")
template <int N>
__device__ __forceinline__ void cp_wait() {
    asm volatile("cp.async.wait_group %0;" :: "n"(N) : "memory");
}

__device__ __forceinline__ void ldsm4(uint32_t addr, uint32_t* r) {
    asm volatile("ldmatrix.sync.aligned.m8n8.x4.shared.b16 {%0,%1,%2,%3}, [%4];"
        : "=r"(r[0]), "=r"(r[1]), "=r"(r[2]), "=r"(r[3]) : "r"(addr));
}

__device__ __forceinline__ void mma_fp16(float* c, const uint32_t* a, const uint32_t* b) {
    asm volatile("mma.sync.aligned.m16n8k16.row.col.f32.f16.f16.f32 "
        "{%0,%1,%2,%3}, {%4,%5,%6,%7}, {%8,%9}, {%0,%1,%2,%3};"
        : "+f"(c[0]), "+f"(c[1]), "+f"(c[2]), "+f"(c[3])
        : "r"(a[0]), "r"(a[1]), "r"(a[2]), "r"(a[3]), "r"(b[0]), "r"(b[1]));
}

// ---------------------------------------------------------------------------
// gates loader: one K-chunk (64 fp16 cols = 128B rows) of A(128) + B(128).
// swizzle: phys_col16 = col16 ^ (row & 7)
// ---------------------------------------------------------------------------
__device__ __forceinline__ void load_stage(uint32_t sbase,
    const char* aP, const char* bP, int lda_b, int ldb_b, int k0b, int tid) {
    const char* srcs[2] = {aP, bP};
    const int lds[2] = {lda_b, ldb_b};
#pragma unroll
    for (int t = 0; t < 2; t++) {
#pragma unroll
        for (int i = 0; i < 4; i++) {
            int idx = i * 256 + tid;
            int row = idx >> 3;
            uint32_t ch = (uint32_t)(idx & 7) * 16;
            uint32_t off = (uint32_t)row * 128 + (ch ^ (((uint32_t)row & 7) << 4));
            cp16(sbase + t * TILE_B + off,
                 srcs[t] + (size_t)row * lds[t] + k0b + ch);
        }
    }
}

// ---------------------------------------------------------------------------
// gates GEMM tile: 128x128, 8 warps (4Mx2N), warp tile 32x64, 3-stage.
// ---------------------------------------------------------------------------
__device__ __forceinline__ void mma_gemm_tile(
    const __half* Ah, int lda, const __half* Bh, int ldb,
    const float* __restrict__ bias, float* __restrict__ C, int ldc,
    int K, int blockM, int blockN) {
    extern __shared__ __align__(1024) char dsm[];
    const int tid  = threadIdx.x;
    const int lane = tid & 31;
    const int wid  = tid >> 5;
    const int wm   = wid & 3;
    const int wn   = wid >> 2;
    uint32_t sb = smem_u32(dsm);

    const uint32_t a_kb = ((uint32_t)lane >> 4) * 16;
    const uint32_t b_kb = (((uint32_t)lane >> 3) & 1) * 16;
    uint32_t aRow[2], aXor[2];
#pragma unroll
    for (int mt = 0; mt < 2; mt++) {
        int r = wm * 32 + mt * 16 + (lane & 15);
        aRow[mt] = (uint32_t)r * 128;
        aXor[mt] = ((uint32_t)r & 7) << 4;
    }
    uint32_t bRow[4], bXor[4];
#pragma unroll
    for (int g = 0; g < 4; g++) {
        int r = wn * 64 + g * 16 + (((lane >> 4) << 3) + (lane & 7));
        bRow[g] = (uint32_t)r * 128;
        bXor[g] = ((uint32_t)r & 7) << 4;
    }

    float acc[2][8][4];
#pragma unroll
    for (int mt = 0; mt < 2; mt++)
#pragma unroll
        for (int nt = 0; nt < 8; nt++)
#pragma unroll
            for (int j = 0; j < 4; j++) acc[mt][nt][j] = 0.0f;

    const char* aP = (const char*)(Ah + (size_t)blockM * lda);
    const char* bP = (const char*)(Bh + (size_t)blockN * ldb);
    const int lda_b = lda * 2, ldb_b = ldb * 2;
    const int NC = K / 64;

    load_stage(sb, aP, bP, lda_b, ldb_b, 0, tid);
    CP_COMMIT();
    load_stage(sb + STAGE_B, aP, bP, lda_b, ldb_b, 128, tid);
    CP_COMMIT();

    int stage = 0;
    for (int c = 0; c < NC; ++c) {
        cp_wait<1>();
        __syncthreads();
        if (c + 2 < NC) {
            int s2 = stage + 2; if (s2 >= NSTAGE) s2 -= NSTAGE;
            load_stage(sb + (uint32_t)s2 * STAGE_B, aP, bP,
                       lda_b, ldb_b, (c + 2) * 128, tid);
        }
        CP_COMMIT();

        const uint32_t st = sb + (uint32_t)stage * STAGE_B;
#pragma unroll
        for (int kk = 0; kk < 4; kk++) {
            uint32_t a[2][4];
#pragma unroll
            for (int mt = 0; mt < 2; mt++) {
                uint32_t col = ((uint32_t)(kk * 32) + a_kb) ^ aXor[mt];
                ldsm4(st + aRow[mt] + col, a[mt]);
            }
            uint32_t b[8][2];
#pragma unroll
            for (int g = 0; g < 4; g++) {
                uint32_t col = ((uint32_t)(kk * 32) + b_kb) ^ bXor[g];
                uint32_t r[4];
                ldsm4(st + TILE_B + bRow[g] + col, r);
                b[2*g][0]   = r[0]; b[2*g][1]   = r[1];
                b[2*g+1][0] = r[2]; b[2*g+1][1] = r[3];
            }
#pragma unroll
            for (int mt = 0; mt < 2; mt++)
#pragma unroll
                for (int nt = 0; nt < 8; nt++)
                    mma_fp16(acc[mt][nt], a[mt], b[nt]);
        }
        if (++stage >= NSTAGE) stage = 0;
    }

#pragma unroll
    for (int mt = 0; mt < 2; mt++) {
        int r0 = blockM + wm * 32 + mt * 16 + (lane >> 2);
#pragma unroll
        for (int nt = 0; nt < 8; nt++) {
            int col = blockN + wn * 64 + nt * 8 + (lane & 3) * 2;
            float b0 = bias[col], b1 = bias[col + 1];
            float2 v0 = {acc[mt][nt][0] + b0, acc[mt][nt][1] + b1};
            float2 v1 = {acc[mt][nt][2] + b0, acc[mt][nt][3] + b1};
            *(float2*)(C + (size_t)r0 * ldc + col) = v0;
            *(float2*)(C + (size_t)(r0 + 8) * ldc + col) = v1;
        }
    }
}

// ---------------------------------------------------------------------------
__global__ __launch_bounds__(256, 2)
void gates_mma_kernel(const float* __restrict__ bi, const float* __restrict__ bo,
                      const float* __restrict__ bc, const float* __restrict__ bf) {
    int z = blockIdx.z;
    const __half* wt; const float* bias; int K; float* dst;
    if      (z == 0) { wt = g_w_h + OFF_WF; bias = bf; K = KD; dst = g_z[3]; }
    else if (z == 1) { wt = g_w_h + OFF_WI; bias = bi; K = KC; dst = g_z[0]; }
    else if (z == 2) { wt = g_w_h + OFF_WO; bias = bo; K = KC; dst = g_z[1]; }
    else             { wt = g_w_h + OFF_WC; bias = bc; K = KC; dst = g_z[2]; }
    mma_gemm_tile(g_comb_h, KD, wt, K, bias, dst, HH, K,
                  blockIdx.y * 128, blockIdx.x * 128);
}

// ---------------------------------------------------------------------------
// out GEMM: 64x64 tile, 8 warps (2Mx4N), warp tile 32x16, 3-stage.
// grid (8, 32) = 256 CTAs -> ~1.7 CTAs/SM for latency hiding.
// ---------------------------------------------------------------------------
__device__ __forceinline__ void load_stage_out(uint32_t sbase,
    const char* aP, const char* bP, int ld_b, int k0b, int tid) {
    const char* srcs[2] = {aP, bP};
#pragma unroll
    for (int t = 0; t < 2; t++) {
#pragma unroll
        for (int i = 0; i < 2; i++) {      // 64 rows x 8 chunks = 512 cp16
            int idx = i * 256 + tid;
            int row = idx >> 3;
            uint32_t ch = (uint32_t)(idx & 7) * 16;
            uint32_t off = (uint32_t)row * 128 + (ch ^ (((uint32_t)row & 7) << 4));
            cp16(sbase + t * OA_TILE_B + off, srcs[t] + (size_t)row * ld_b + k0b + ch);
        }
    }
}

__global__ __launch_bounds__(256, 3)
void out_mma_kernel(const float* __restrict__ bout, float* __restrict__ out) {
    extern __shared__ __align__(1024) char dsm[];
    const int tid  = threadIdx.x;
    const int lane = tid & 31;
    const int wid  = tid >> 5;
    const int wm   = wid & 1;    // 0..1 -> 32-row slab
    const int wn   = wid >> 1;   // 0..3 -> 16-col slab
    const int blockM = blockIdx.y * 64;
    const int blockN = blockIdx.x * 64;
    uint32_t sb = smem_u32(dsm);

    const uint32_t a_kb = ((uint32_t)lane >> 4) * 16;
    const uint32_t b_kb = (((uint32_t)lane >> 3) & 1) * 16;
    uint32_t aRow[2], aXor[2];
#pragma unroll
    for (int mt = 0; mt < 2; mt++) {
        int r = wm * 32 + mt * 16 + (lane & 15);
        aRow[mt] = (uint32_t)r * 128;
        aXor[mt] = ((uint32_t)r & 7) << 4;
    }
    uint32_t bRow, bXor;
    {
        int r = wn * 16 + (((lane >> 4) << 3) + (lane & 7));
        bRow = (uint32_t)r * 128;
        bXor = ((uint32_t)r & 7) << 4;
    }

    float acc[2][2][4];
#pragma unroll
    for (int mt = 0; mt < 2; mt++)
#pragma unroll
        for (int nt = 0; nt < 2; nt++)
#pragma unroll
            for (int j = 0; j < 4; j++) acc[mt][nt][j] = 0.0f;

    const char* aP = (const char*)(g_hid_h + (size_t)blockM * HH);
    const char* bP = (const char*)(g_w_h + OFF_WOUT + (size_t)blockN * HH);
    const int ld_b = HH * 2;
    const int NC = HH / 64;   // 8

    load_stage_out(sb, aP, bP, ld_b, 0, tid);
    CP_COMMIT();
    load_stage_out(sb + OSTAGE_B, aP, bP, ld_b, 128, tid);
    CP_COMMIT();

    int stage = 0;
    for (int c = 0; c < NC; ++c) {
        cp_wait<1>();
        __syncthreads();
        if (c + 2 < NC) {
            int s2 = stage + 2; if (s2 >= NSTAGE) s2 -= NSTAGE;
            load_stage_out(sb + (uint32_t)s2 * OSTAGE_B, aP, bP,
                           ld_b, (c + 2) * 128, tid);
        }
        CP_COMMIT();

        const uint32_t st = sb + (uint32_t)stage * OSTAGE_B;
#pragma unroll
        for (int kk = 0; kk < 4; kk++) {
            uint32_t a[2][4];
#pragma unroll
            for (int mt = 0; mt < 2; mt++) {
                uint32_t col = ((uint32_t)(kk * 32) + a_kb) ^ aXor[mt];
                ldsm4(st + aRow[mt] + col, a[mt]);
            }
            uint32_t b[2][2];
            {
                uint32_t col = ((uint32_t)(kk * 32) + b_kb) ^ bXor;
                uint32_t r[4];
                ldsm4(st + OA_TILE_B + bRow + col, r);
                b[0][0] = r[0]; b[0][1] = r[1];
                b[1][0] = r[2]; b[1][1] = r[3];
            }
#pragma unroll
            for (int mt = 0; mt < 2; mt++)
#pragma unroll
                for (int nt = 0; nt < 2; nt++)
                    mma_fp16(acc[mt][nt], a[mt], b[nt]);
        }
        if (++stage >= NSTAGE) stage = 0;
    }

#pragma unroll
    for (int mt = 0; mt < 2; mt++) {
        int r0 = blockM + wm * 32 + mt * 16 + (lane >> 2);
#pragma unroll
        for (int nt = 0; nt < 2; nt++) {
            int col = blockN + wn * 16 + nt * 8 + (lane & 3) * 2;
            float b0 = bout[col], b1 = bout[col + 1];
            float2 v0 = {acc[mt][nt][0] + b0, acc[mt][nt][1] + b1};
            float2 v1 = {acc[mt][nt][2] + b0, acc[mt][nt][3] + b1};
            *(float2*)(out + (size_t)r0 * OUTN + col) = v0;
            *(float2*)(out + (size_t)(r0 + 8) * OUTN + col) = v1;
        }
    }
}

// ---------------------------------------------------------------------------
// merged conversion kernel: fp32 -> fp16 for combined_d AND all 5 weights.
// ---------------------------------------------------------------------------
__device__ __forceinline__ void cvt4h(float4 v, __half* dst) {
    union { __half h[4]; uint2 u; } H;
    H.h[0] = __float2half_rn(v.x);
    H.h[1] = __float2half_rn(v.y);
    H.h[2] = __float2half_rn(v.z);
    H.h[3] = __float2half_rn(v.w);
    *(uint2*)dst = H.u;
}

__global__ void conv_all_kernel(const float* __restrict__ sample,
                                const float* __restrict__ hidden,
                                const float* __restrict__ d0,
                                const float* __restrict__ Wi,
                                const float* __restrict__ Wo,
                                const float* __restrict__ Wc,
                                const float* __restrict__ Wf,
                                const float* __restrict__ Wout) {
    int idx = blockIdx.x * blockDim.x + threadIdx.x;
    if (idx >= CVF4_TOTAL) return;

    if (idx < CVF4_COMB) {
        int b  = idx / (KD / 4);
        int c4 = idx % (KD / 4);
        float4 v;
        if (c4 < INN / 4)            v = ((const float4*)sample)[b * (INN/4) + c4];
        else if (c4 < (INN+HH) / 4)  v = ((const float4*)hidden)[b * (HH/4) + (c4 - INN/4)];
        else                         v = ((const float4*)d0)[b * (HH/4) + (c4 - (INN+HH)/4)];
        cvt4h(v, g_comb_h + (size_t)idx * 4);
        return;
    }
    int r = idx - CVF4_COMB;
    const float* src; size_t off4;
    if      (r < CVF4_W1)            { src = Wi;   off4 = 0;                         }
    else if (r < 2*CVF4_W1)          { src = Wo;   off4 = CVF4_W1;   r -= CVF4_W1;   }
    else if (r < 3*CVF4_W1)          { src = Wc;   off4 = 2*CVF4_W1; r -= 2*CVF4_W1; }
    else if (r < 3*CVF4_W1+CVF4_WF)  { src = Wf;   off4 = 3*CVF4_W1; r -= 3*CVF4_W1; }
    else                             { src = Wout; off4 = 3*CVF4_W1+CVF4_WF; r -= 3*CVF4_W1+CVF4_WF; }
    float4 v = ((const float4*)src)[r];
    cvt4h(v, g_w_h + (off4 + (size_t)r) * 4);
}

// ---------------------------------------------------------------------------
// fused elementwise: 4-slice batched loads/stores (MLP=4) + streaming hints
// ---------------------------------------------------------------------------
__device__ __forceinline__ float sigf(float x) { return 1.0f / (1.0f + expf(-x)); }

__global__ void fused_cell_kernel(const float* __restrict__ cell_t,
                                  float* __restrict__ dout) {
    int idx = blockIdx.x * blockDim.x + threadIdx.x;   // over BH/4
    const int nb4 = BH / 4;
    if (idx >= nb4) return;

    const float4* c4  = (const float4*)cell_t;
    float4* hid = (float4*)(dout + (size_t)BB * OUTN);
    float4* hc  = (float4*)(dout + (size_t)2 * BB * OUTN);
    float4* dv  = (float4*)(dout + (size_t)2 * BB * OUTN + (size_t)KFR * BH);

    float4 zf = ((const float4*)g_z[3])[idx];
    float4 d;
    d.x = 0.5f * sigf(zf.x); d.y = 0.5f * sigf(zf.y);
    d.z = 0.5f * sigf(zf.z); d.w = 0.5f * sigf(zf.w);
    __stcs(&dv[idx], d);

    float4 w   = make_float4(1.f, 1.f, 1.f, 1.f);
    float4 acc = make_float4(0.f, 0.f, 0.f, 0.f);
#pragma unroll
    for (int jb = KFR - 1; jb >= 3; jb -= 4) {
        float4 buf[4];
#pragma unroll
        for (int u = 0; u < 4; u++)
            buf[u] = __ldcs(&c4[(size_t)(jb - u) * nb4 + idx]);
#pragma unroll
        for (int u = 0; u < 4; u++) {
            int j = jb - u;
            float fi  = (float)(KFR - 1 - j);
            float inv = 1.0f / (float)(KFR - j);
            w.x *= (fi - d.x) * inv;  w.y *= (fi - d.y) * inv;
            w.z *= (fi - d.z) * inv;  w.w *= (fi - d.w) * inv;
            acc.x = fmaf(w.x, buf[u].x, acc.x);  acc.y = fmaf(w.y, buf[u].y, acc.y);
            acc.z = fmaf(w.z, buf[u].z, acc.z);  acc.w = fmaf(w.w, buf[u].w, acc.w);
            if (j >= 1) __stcs(&hc[(size_t)(j - 1) * nb4 + idx], buf[u]);
        }
    }

    float4 zi = ((const float4*)g_z[0])[idx];
    float4 zo = ((const float4*)g_z[1])[idx];
    float4 zc = ((const float4*)g_z[2])[idx];

    float4 cell;
    cell.x = -acc.x + tanhf(zc.x) * sigf(zi.x);
    cell.y = -acc.y + tanhf(zc.y) * sigf(zi.y);
    cell.z = -acc.z + tanhf(zc.z) * sigf(zi.z);
    cell.w = -acc.w + tanhf(zc.w) * sigf(zi.w);
    __stcs(&hc[(size_t)(KFR - 1) * nb4 + idx], cell);

    float4 hn;
    hn.x = tanhf(cell.x) * sigf(zo.x);
    hn.y = tanhf(cell.y) * sigf(zo.y);
    hn.z = tanhf(cell.z) * sigf(zo.z);
    hn.w = tanhf(cell.w) * sigf(zo.w);
    __stcs(&hid[idx], hn);

    cvt4h(hn, g_hid_h + (size_t)idx * 4);
}

// ---------------------------------------------------------------------------
extern "C" void kernel_launch(void* const* d_in, const int* in_sizes, int n_in,
                              void* d_out_v, int out_size) {
    const float* sample = (const float*)d_in[0];
    const float* hidden = (const float*)d_in[1];
    const float* cell_t = (const float*)d_in[2];
    const float* d0     = (const float*)d_in[3];
    const float* Wc     = (const float*)d_in[4];
    const float* bc     = (const float*)d_in[5];
    const float* Wi     = (const float*)d_in[6];
    const float* bi     = (const float*)d_in[7];
    const float* Wf     = (const float*)d_in[8];
    const float* bf     = (const float*)d_in[9];
    const float* Wo     = (const float*)d_in[10];
    const float* bo     = (const float*)d_in[11];
    const float* Wout   = (const float*)d_in[12];
    const float* bout   = (const float*)d_in[13];
    float* out = (float*)d_out_v;

    cudaFuncSetAttribute(gates_mma_kernel,
                         cudaFuncAttributeMaxDynamicSharedMemorySize, SMEM_TOT);
    cudaFuncSetAttribute(out_mma_kernel,
                         cudaFuncAttributeMaxDynamicSharedMemorySize, OSMEM_TOT);

    // 1) merged fp16 conversion of combined_d + all weights
    conv_all_kernel<<<(CVF4_TOTAL + 255) / 256, 256>>>(
        sample, hidden, d0, Wi, Wo, Wc, Wf, Wout);

    // 2) 4 gate GEMMs, single-pass fp16, 2 CTAs/SM -> single wave
    dim3 ggrid(4, 16, 4);
    gates_mma_kernel<<<ggrid, 256, SMEM_TOT>>>(bi, bo, bc, bf);

    // 3) fused elementwise (batched, streaming) + fp16 hidden
    fused_cell_kernel<<<(BH / 4 + 255) / 256, 256>>>(cell_t, out);

    // 4) output GEMM, 64x64 tiles -> 256 CTAs
    dim3 ogrid(8, 32);
    out_mma_kernel<<<ogrid, 256, OSMEM_TOT>>>(bout, out);
}